// round 6
// baseline (speedup 1.0000x reference)
#include <cuda_runtime.h>
#include <cstdint>

// x: (8, 64, 128, 128) fp32  ->  out: (8, 64, 384, 384) fp32
//
// Row dedup: distinct output rows are center(i)=Hresample(x[i]) -> row 3i+1,
// avg(i)=Hresample(0.5*(x[i]+x[i+1])) -> rows 3i+2 and 3i+3; row 0 = avg(0),
// rows 382/383 = center(127)/avg(126).
// Hresample: out col 3j+kj: kj=0 -> h[j-1], kj=1 -> c[j], kj=2 -> h[j];
// h[j]=0.5*(c[j]+c[refl(j+1)]); reflect: -1 -> 1, 128 -> 126.
//
// Warp per input row: LDG -> blend -> padded smem (Cs) -> gather -> staged
// output rows in smem (Or) -> TMA bulk stores (cp.async.bulk). Duplicate
// output rows are extra bulk copies from the SAME smem row (gather once).
// Global stores ride the TMA path instead of 36 LSU wavefronts/warp.

#define H 128
#define W 128
#define W4 (W / 4)
#define OW 384
#define OW4 (OW / 4)
#define NW 8
#define CPAD 144              // 128 + 4 pad per 32 floats (keeps 16B align)
#define ROWB (OW * 4)         // 1536 bytes per output row

__device__ __forceinline__ int swz(int j) { return j + ((j >> 5) << 2); }

__device__ __forceinline__ float4 gatherv(const float* __restrict__ C,
                                          int aq, int aq1, int at, int r)
{
    const float cq  = C[aq];
    const float cq1 = C[aq1];
    const float ct  = C[at];

    const float h0 = 0.5f * (cq + cq1);
    const float ex = 0.5f * (ct + ((r == 0) ? cq : cq1));

    float4 v;
    v.x = (r == 0) ? ex  : ((r == 1) ? cq  : h0);
    v.y = (r == 0) ? cq  : h0;
    v.z = (r == 2) ? cq1 : h0;
    v.w = (r == 2) ? ex  : ((r == 1) ? cq1 : h0);
    return v;
}

__device__ __forceinline__ void bulk_store_row(const float* gdst, uint32_t ssrc)
{
    asm volatile(
        "cp.async.bulk.global.shared::cta.bulk_group [%0], [%1], %2;"
        :: "l"(gdst), "r"(ssrc), "r"(ROWB) : "memory");
}

__global__ __launch_bounds__(NW * 32) void rf_scale_kernel(
    const float4* __restrict__ x, float4* __restrict__ out)
{
    __shared__ float Cs[NW][2][CPAD];                  // blended source rows
    __shared__ __align__(16) float Or[NW][2][OW];      // staged output rows

    const int lane = threadIdx.x & 31;
    const int w    = threadIdx.x >> 5;

    const int i  = blockIdx.x * NW + w;                // input row 0..127
    const int bc = blockIdx.y;

    const float4* __restrict__ xin = x + (size_t)bc * (H * W4);

    // i<127: avg(i) with row i+1; i==127: compute avg(126) for row 383.
    const int i1 = (i < H - 1) ? i + 1 : i - 1;
    const float4 b = xin[i  * W4 + lane];
    const float4 d = xin[i1 * W4 + lane];

    float4 av;
    av.x = 0.5f * (b.x + d.x);
    av.y = 0.5f * (b.y + d.y);
    av.z = 0.5f * (b.z + d.z);
    av.w = 0.5f * (b.w + d.w);

    const int so = swz(lane << 2);
    *reinterpret_cast<float4*>(&Cs[w][0][so]) = b;     // center source
    *reinterpret_cast<float4*>(&Cs[w][1][so]) = av;    // avg source
    __syncwarp();

    const float* __restrict__ Cc = Cs[w][0];
    const float* __restrict__ Ca = Cs[w][1];
    float4* __restrict__ OutC = reinterpret_cast<float4*>(Or[w][0]);
    float4* __restrict__ OutA = reinterpret_cast<float4*>(Or[w][1]);

    #pragma unroll
    for (int s = 0; s < 3; s++) {
        const int g  = lane + (s << 5);                       // 0..95
        const int fg = g << 2;
        const int q  = (int)(((unsigned)fg * 21846u) >> 16);  // fg/3 (exact)
        const int r  = fg - 3 * q;

        const int qt = (r == 0) ? ((q == 0) ? 1 : q - 1)
                                : ((q == W - 2) ? (W - 2) : q + 2);

        const int aq  = swz(q);
        const int aq1 = swz(q + 1);
        const int at  = swz(qt);

        OutC[g] = gatherv(Cc, aq, aq1, at, r);
        OutA[g] = gatherv(Ca, aq, aq1, at, r);
    }
    __syncwarp();

    if (lane == 0) {
        asm volatile("fence.proxy.async.shared::cta;" ::: "memory");

        const float* obase = reinterpret_cast<const float*>(out)
                           + (size_t)bc * (OW * OW) + (size_t)(3 * i) * OW;

        const uint32_t sc = (uint32_t)__cvta_generic_to_shared(Or[w][0]);
        const uint32_t sa = (uint32_t)__cvta_generic_to_shared(Or[w][1]);

        bulk_store_row(obase + OW,     sc);   // row 3i+1 : center(i)
        bulk_store_row(obase + 2 * OW, sa);   // row 3i+2 : avg
        if (i < H - 1) bulk_store_row(obase + 3 * OW, sa);   // row 3i+3
        if (i == 0)    bulk_store_row(obase - 0 * OW + 0, sa); // row 0 = avg(0)

        asm volatile("cp.async.bulk.commit_group;" ::: "memory");
        asm volatile("cp.async.bulk.wait_group 0;" ::: "memory");
    }
}

extern "C" void kernel_launch(void* const* d_in, const int* in_sizes, int n_in,
                              void* d_out, int out_size)
{
    const float4* x = (const float4*)d_in[0];
    float4* out = (float4*)d_out;

    const int n_bc = in_sizes[0] / (H * W);   // 512

    dim3 grid(H / NW, n_bc);                  // (16, 512)
    dim3 block(NW * 32);                      // 256
    rf_scale_kernel<<<grid, block>>>(x, out);
}

// round 7
// speedup vs baseline: 1.0756x; 1.0756x over previous
#include <cuda_runtime.h>

// x: (8, 64, 128, 128) fp32  ->  out: (8, 64, 384, 384) fp32
//
// Row dedup: distinct output rows are center(i)=Hresample(x[i]) -> row 3i+1,
// avg(i)=Hresample(0.5*(x[i]+x[i+1])) -> rows 3i+2 and 3i+3; row 0 = avg(0),
// rows 382/383 = center(127)/avg(126).
// Hresample: out col 3j+kj: kj=0 -> h[j-1], kj=1 -> c[j], kj=2 -> h[j];
// h[j] = 0.5*(c[j]+c[refl(j+1)]); reflect: -1 -> 1, 128 -> 126.
//
// Warp per input row i: 2x LDG.128, blend, 2x STS.128 into padded smem,
// gather indices computed once per output-vec and reused for center/avg rows;
// all output stores are coalesced full-sector STG.128 with .cs (streaming,
// evict-first) since the 302MB output is never re-read.

#define H 128
#define W 128
#define W4 (W / 4)
#define OW 384
#define OW4 (OW / 4)
#define NW 8
#define CPAD 144              // 128 + 4 pad per 32 floats (keeps 16B align)

__device__ __forceinline__ int swz(int j) { return j + ((j >> 5) << 2); }

__device__ __forceinline__ float4 gatherv(const float* __restrict__ C,
                                          int aq, int aq1, int at, int r)
{
    const float cq  = C[aq];
    const float cq1 = C[aq1];
    const float ct  = C[at];

    const float h0 = 0.5f * (cq + cq1);
    const float ex = 0.5f * (ct + ((r == 0) ? cq : cq1));

    float4 v;
    v.x = (r == 0) ? ex  : ((r == 1) ? cq  : h0);
    v.y = (r == 0) ? cq  : h0;
    v.z = (r == 2) ? cq1 : h0;
    v.w = (r == 2) ? ex  : ((r == 1) ? cq1 : h0);
    return v;
}

__global__ __launch_bounds__(NW * 32) void rf_scale_kernel(
    const float4* __restrict__ x, float4* __restrict__ out)
{
    __shared__ float Cs[NW][2][CPAD];   // [0] = center row, [1] = avg row

    const int lane = threadIdx.x & 31;
    const int w    = threadIdx.x >> 5;

    const int i  = blockIdx.x * NW + w;          // input row 0..127
    const int bc = blockIdx.y;

    const float4* __restrict__ xin = x + (size_t)bc * (H * W4);

    // i<127: avg(i) with row i+1; i==127: compute avg(126) for row 383.
    const int i1 = (i < H - 1) ? i + 1 : i - 1;
    const float4 b = xin[i  * W4 + lane];
    const float4 d = xin[i1 * W4 + lane];

    float4 av;
    av.x = 0.5f * (b.x + d.x);
    av.y = 0.5f * (b.y + d.y);
    av.z = 0.5f * (b.z + d.z);
    av.w = 0.5f * (b.w + d.w);

    const int so = swz(lane << 2);
    *reinterpret_cast<float4*>(&Cs[w][0][so]) = b;
    *reinterpret_cast<float4*>(&Cs[w][1][so]) = av;
    __syncwarp();

    const float* __restrict__ Cc = Cs[w][0];
    const float* __restrict__ Ca = Cs[w][1];

    float4* __restrict__ obase =
        out + (size_t)bc * (OW * OW4) + (size_t)(3 * i) * OW4;

    const bool last = (i == H - 1);

    #pragma unroll
    for (int s = 0; s < 3; s++) {
        const int g  = lane + (s << 5);                       // 0..95
        const int fg = g << 2;
        const int q  = (int)(((unsigned)fg * 21846u) >> 16);  // fg/3 (exact)
        const int r  = fg - 3 * q;

        const int qt = (r == 0) ? ((q == 0) ? 1 : q - 1)
                                : ((q == W - 2) ? (W - 2) : q + 2);

        const int aq  = swz(q);
        const int aq1 = swz(q + 1);
        const int at  = swz(qt);

        // center(i) -> row 3i+1
        __stcs(&obase[OW4 + g], gatherv(Cc, aq, aq1, at, r));

        const float4 v = gatherv(Ca, aq, aq1, at, r);
        if (!last) {
            __stcs(&obase[2 * OW4 + g], v);           // row 3i+2 = avg(i)
            __stcs(&obase[3 * OW4 + g], v);           // row 3i+3 = avg(i)
            if (i == 0) __stcs(&obase[g], v);         // row 0    = avg(0)
        } else {
            __stcs(&obase[2 * OW4 + g], v);           // row 383  = avg(126)
        }
    }
}

extern "C" void kernel_launch(void* const* d_in, const int* in_sizes, int n_in,
                              void* d_out, int out_size)
{
    const float4* x = (const float4*)d_in[0];
    float4* out = (float4*)d_out;

    const int n_bc = in_sizes[0] / (H * W);   // 512

    dim3 grid(H / NW, n_bc);                  // (16, 512)
    dim3 block(NW * 32);                      // 256
    rf_scale_kernel<<<grid, block>>>(x, out);
}